// round 13
// baseline (speedup 1.0000x reference)
#include <cuda_runtime.h>
#include <cuda_bf16.h>
#include <math.h>

// Problem constants
#define BB 2
#define TT 2048
#define CC 2048
#define HH 16
#define DD 128
#define NTOK (BB*TT)      // 4096
#define C3 (3*CC)         // 6144

// Scratch (static device allocations; no cudaMalloc allowed)
__device__ float g_qkv[(size_t)NTOK * C3];    // ~100 MB
__device__ float g_attn[(size_t)NTOK * CC];   // ~33 MB

// ---------------------------------------------------------------------------
// SGEMM  C[M,N] = A[M,K] * B[N,K]^T  (validated across two independent impls)
// 128x128 tile, BK=16, 256 threads, 8x8 microtile per thread.
// ---------------------------------------------------------------------------
#define BM 128
#define BN 128
#define BK 16
#define TM 8
#define TN 8

__global__ __launch_bounds__(256) void gemm_nt(
    const float* __restrict__ A, const float* __restrict__ B,
    float* __restrict__ C, int M, int N, int K)
{
    __shared__ float As[BK][BM];
    __shared__ float Bs[BK][BN];

    const int tid = threadIdx.x;
    const int m0 = blockIdx.y * BM;
    const int n0 = blockIdx.x * BN;
    const int tx = tid & 15;
    const int ty = tid >> 4;

    float acc[TM][TN];
#pragma unroll
    for (int i = 0; i < TM; i++)
#pragma unroll
        for (int j = 0; j < TN; j++) acc[i][j] = 0.f;

    for (int k0 = 0; k0 < K; k0 += BK) {
#pragma unroll
        for (int it = 0; it < 2; it++) {
            int idx = tid + it * 256;
            int row = idx >> 2;
            int kq  = idx & 3;
            float4 v = *(const float4*)&A[(size_t)(m0 + row) * K + k0 + kq * 4];
            As[kq*4+0][row] = v.x; As[kq*4+1][row] = v.y;
            As[kq*4+2][row] = v.z; As[kq*4+3][row] = v.w;
        }
#pragma unroll
        for (int it = 0; it < 2; it++) {
            int idx = tid + it * 256;
            int row = idx >> 2;
            int kq  = idx & 3;
            float4 v = *(const float4*)&B[(size_t)(n0 + row) * K + k0 + kq * 4];
            Bs[kq*4+0][row] = v.x; Bs[kq*4+1][row] = v.y;
            Bs[kq*4+2][row] = v.z; Bs[kq*4+3][row] = v.w;
        }
        __syncthreads();

#pragma unroll
        for (int k = 0; k < BK; k++) {
            float ra[TM], rb[TN];
#pragma unroll
            for (int i = 0; i < TM; i += 4) {
                float4 v = *(const float4*)&As[k][ty*TM + i];
                ra[i] = v.x; ra[i+1] = v.y; ra[i+2] = v.z; ra[i+3] = v.w;
            }
#pragma unroll
            for (int j = 0; j < TN; j += 4) {
                float4 v = *(const float4*)&Bs[k][tx*TN + j];
                rb[j] = v.x; rb[j+1] = v.y; rb[j+2] = v.z; rb[j+3] = v.w;
            }
#pragma unroll
            for (int i = 0; i < TM; i++)
#pragma unroll
                for (int j = 0; j < TN; j++)
                    acc[i][j] += ra[i] * rb[j];
        }
        __syncthreads();
    }

#pragma unroll
    for (int i = 0; i < TM; i++) {
#pragma unroll
        for (int j = 0; j < TN; j += 4) {
            float4 v = make_float4(acc[i][j], acc[i][j+1], acc[i][j+2], acc[i][j+3]);
            *(float4*)&C[(size_t)(m0 + ty*TM + i) * N + n0 + tx*TN + j] = v;
        }
    }
}

// ---------------------------------------------------------------------------
// RoPE, half-split pairing (i, i+64), REVERSED rotation (theta -> -theta):
//   e' =  e*cos + o*sin
//   o' = -e*sin + o*cos
// Angle in fp64 (exact), reduced mod 2pi, fp32 sincos.
// ---------------------------------------------------------------------------
__global__ void rope_rev_kernel(float* __restrict__ qkv,
                                const int* __restrict__ start_pos)
{
    const int half = DD / 2;  // 64
    int idx = blockIdx.x * blockDim.x + threadIdx.x;
    int total = NTOK * HH * half;
    if (idx >= total) return;

    int i = idx % half;
    int h = (idx / half) % HH;
    int n = idx / (half * HH);
    int t = n % TT;

    double pos = (double)(*start_pos + t);
    double inv_freq = exp2(-(double)i * (13.287712379549449 / 64.0)); // 1e4^(-i/64)
    double ang = pos * inv_freq;
    const double TWOPI = 6.283185307179586476925286766559;
    ang -= floor(ang / TWOPI) * TWOPI;
    float c, s;
    sincosf((float)ang, &c, &s);

    float* qrow = qkv + (size_t)n * C3 + h * DD;
    float* krow = qrow + CC;

    float q1 = qrow[i], q2 = qrow[i + half];
    qrow[i]        =  q1 * c + q2 * s;     // REVERSED rotation
    qrow[i + half] = -q1 * s + q2 * c;

    float k1 = krow[i], k2 = krow[i + half];
    krow[i]        =  k1 * c + k2 * s;
    krow[i + half] = -k1 * s + k2 * c;
}

// ---------------------------------------------------------------------------
// Causal flash attention, fp32 (machinery validated).
// Grid: (T/64, B*H). Block: 256. 4 lanes per query row; lane owns an
// interleaved quarter of d.
// ---------------------------------------------------------------------------
#define AT_BM 64
#define AT_BN 32

__global__ __launch_bounds__(256) void attn_kernel(
    const float* __restrict__ qkv, float* __restrict__ out)
{
    __shared__ float Ks[AT_BN][DD];
    __shared__ float Vs[AT_BN][DD];

    const int q0 = ((int)gridDim.x - 1 - (int)blockIdx.x) * AT_BM;
    const int bh = blockIdx.y;
    const int b = bh / HH, h = bh % HH;
    const int tid = threadIdx.x;
    const int r = tid >> 2;
    const int lane4 = tid & 3;

    const float scale = 0.08838834764831845f;  // 1/sqrt(128)
    const int qrow = q0 + r;

    const float* qptr = qkv + ((size_t)(b * TT + qrow)) * C3 + h * DD;
    float qreg[32];
#pragma unroll
    for (int i = 0; i < 8; i++) {
        float4 v = *(const float4*)&qptr[4 * (lane4 + 4 * i)];
        qreg[4*i+0] = v.x * scale; qreg[4*i+1] = v.y * scale;
        qreg[4*i+2] = v.z * scale; qreg[4*i+3] = v.w * scale;
    }

    float o[32];
#pragma unroll
    for (int i = 0; i < 32; i++) o[i] = 0.f;
    float m = -1e30f, l = 0.f;

    const float* kbase = qkv + ((size_t)(b * TT)) * C3 + CC     + h * DD;
    const float* vbase = qkv + ((size_t)(b * TT)) * C3 + 2 * CC + h * DD;

    const int kv_end = q0 + AT_BM;
    for (int j0 = 0; j0 < kv_end; j0 += AT_BN) {
        __syncthreads();
#pragma unroll
        for (int it = 0; it < 4; it++) {
            int idx = tid + it * 256;
            int row = idx >> 5;
            int col = idx & 31;
            *(float4*)&Ks[row][col * 4] =
                *(const float4*)&kbase[(size_t)(j0 + row) * C3 + col * 4];
            *(float4*)&Vs[row][col * 4] =
                *(const float4*)&vbase[(size_t)(j0 + row) * C3 + col * 4];
        }
        __syncthreads();

        float s[AT_BN];
#pragma unroll
        for (int j = 0; j < AT_BN; j++) {
            float acc = 0.f;
#pragma unroll
            for (int i = 0; i < 8; i++) {
                const float4 kv4 = *(const float4*)&Ks[j][4 * (lane4 + 4 * i)];
                acc += qreg[4*i+0] * kv4.x + qreg[4*i+1] * kv4.y
                     + qreg[4*i+2] * kv4.z + qreg[4*i+3] * kv4.w;
            }
            acc += __shfl_xor_sync(0xffffffffu, acc, 1);
            acc += __shfl_xor_sync(0xffffffffu, acc, 2);
            s[j] = (j0 + j <= qrow) ? acc : -1e30f;   // causal
        }

        float tm = m;
#pragma unroll
        for (int j = 0; j < AT_BN; j++) tm = fmaxf(tm, s[j]);
        float corr = __expf(m - tm);
        m = tm;
        l *= corr;
#pragma unroll
        for (int i = 0; i < 32; i++) o[i] *= corr;
#pragma unroll
        for (int j = 0; j < AT_BN; j++) {
            float p = __expf(s[j] - m);
            l += p;
            s[j] = p;
        }
#pragma unroll
        for (int j = 0; j < AT_BN; j++) {
            float p = s[j];
#pragma unroll
            for (int i = 0; i < 8; i++) {
                const float4 v4 = *(const float4*)&Vs[j][4 * (lane4 + 4 * i)];
                o[4*i+0] += p * v4.x; o[4*i+1] += p * v4.y;
                o[4*i+2] += p * v4.z; o[4*i+3] += p * v4.w;
            }
        }
    }

    const float inv_l = 1.f / l;
    float* optr = out + ((size_t)(b * TT + qrow)) * CC + h * DD;
#pragma unroll
    for (int i = 0; i < 8; i++) {
        float4 v = make_float4(o[4*i] * inv_l, o[4*i+1] * inv_l,
                               o[4*i+2] * inv_l, o[4*i+3] * inv_l);
        *(float4*)&optr[4 * (lane4 + 4 * i)] = v;
    }
}

// ---------------------------------------------------------------------------
extern "C" void kernel_launch(void* const* d_in, const int* in_sizes, int n_in,
                              void* d_out, int out_size)
{
    const float* x = nullptr;
    const float* Wqkv = nullptr;
    const float* Wproj = nullptr;
    const int* start_pos = nullptr;
    for (int i = 0; i < n_in; i++) {
        long long sz = in_sizes[i];
        if (sz == (long long)NTOK * CC)      x = (const float*)d_in[i];
        else if (sz == (long long)C3 * CC)   Wqkv = (const float*)d_in[i];
        else if (sz == (long long)CC * CC)   Wproj = (const float*)d_in[i];
        else if (sz == 1)                    start_pos = (const int*)d_in[i];
    }
    if (n_in != 4 || !x || !Wqkv || !Wproj || !start_pos ||
        out_size != NTOK * CC)
        return;

    float* out = (float*)d_out;

    void* p;
    cudaGetSymbolAddress(&p, g_qkv);  float* qkv  = (float*)p;
    cudaGetSymbolAddress(&p, g_attn); float* attn = (float*)p;

    // 1) qkv = x @ Wqkv^T
    gemm_nt<<<dim3(C3 / BN, NTOK / BM), 256>>>(x, Wqkv, qkv, NTOK, C3, CC);

    // 2) RoPE, half-split pairing, REVERSED rotation
    {
        int total = NTOK * HH * (DD / 2);
        rope_rev_kernel<<<(total + 255) / 256, 256>>>(qkv, start_pos);
    }

    // 3) causal flash attention
    attn_kernel<<<dim3(TT / AT_BM, BB * HH), 256>>>(qkv, attn);

    // 4) out = attn @ Wproj^T
    gemm_nt<<<dim3(CC / BN, NTOK / BM), 256>>>(attn, Wproj, out, NTOK, CC, CC);
}

// round 15
// speedup vs baseline: 1.4838x; 1.4838x over previous
#include <cuda_runtime.h>
#include <cuda_bf16.h>
#include <math.h>
#include <stdint.h>

// Problem constants
#define BB 2
#define TT 2048
#define CC 2048
#define HH 16
#define DD 128
#define NTOK (BB*TT)      // 4096
#define C3 (3*CC)         // 6144

// fp32 scratch
__device__ float g_qkv[(size_t)NTOK * C3];
__device__ float g_attn[(size_t)NTOK * CC];
// bf16 hi/lo scratch
__device__ __nv_bfloat16 g_xh[(size_t)NTOK * CC],  g_xl[(size_t)NTOK * CC];
__device__ __nv_bfloat16 g_wqh[(size_t)C3 * CC],   g_wql[(size_t)C3 * CC];
__device__ __nv_bfloat16 g_wph[(size_t)CC * CC],   g_wpl[(size_t)CC * CC];
__device__ __nv_bfloat16 g_ah[(size_t)NTOK * CC],  g_al[(size_t)NTOK * CC];

// ===========================================================================
// helpers
// ===========================================================================
__device__ __forceinline__ uint32_t smem_to_u32(const void* p) {
    uint32_t a;
    asm("{ .reg .u64 t; cvta.to.shared.u64 t, %1; cvt.u32.u64 %0, t; }"
        : "=r"(a) : "l"(p));
    return a;
}
__device__ __forceinline__ void ldmatrix_x4(uint32_t* r, uint32_t addr) {
    asm volatile("ldmatrix.sync.aligned.m8n8.x4.shared.b16 {%0,%1,%2,%3}, [%4];"
                 : "=r"(r[0]), "=r"(r[1]), "=r"(r[2]), "=r"(r[3]) : "r"(addr));
}
__device__ __forceinline__ void ldmatrix_x2(uint32_t* r, uint32_t addr) {
    asm volatile("ldmatrix.sync.aligned.m8n8.x2.shared.b16 {%0,%1}, [%2];"
                 : "=r"(r[0]), "=r"(r[1]) : "r"(addr));
}
__device__ __forceinline__ void mma_bf16(float* c, const uint32_t* a, const uint32_t* b) {
    asm volatile(
        "mma.sync.aligned.m16n8k16.row.col.f32.bf16.bf16.f32 "
        "{%0,%1,%2,%3}, {%4,%5,%6,%7}, {%8,%9}, {%0,%1,%2,%3};"
        : "+f"(c[0]), "+f"(c[1]), "+f"(c[2]), "+f"(c[3])
        : "r"(a[0]), "r"(a[1]), "r"(a[2]), "r"(a[3]), "r"(b[0]), "r"(b[1]));
}
#define CP_ASYNC16(dst_u32, src) \
    asm volatile("cp.async.cg.shared.global [%0], [%1], 16;" \
                 :: "r"(dst_u32), "l"(src) : "memory")
#define CP_COMMIT() asm volatile("cp.async.commit_group;" ::: "memory")
#define CP_WAIT(n)  asm volatile("cp.async.wait_group %0;" :: "n"(n) : "memory")

// ===========================================================================
// fp32 -> bf16 hi/lo split
// ===========================================================================
__global__ __launch_bounds__(256) void split_bf16(
    const float* __restrict__ in, __nv_bfloat16* __restrict__ hi,
    __nv_bfloat16* __restrict__ lo, int n4)
{
    int i = blockIdx.x * blockDim.x + threadIdx.x;
    if (i >= n4) return;
    float4 v = ((const float4*)in)[i];
    __nv_bfloat16 h0 = __float2bfloat16_rn(v.x);
    __nv_bfloat16 h1 = __float2bfloat16_rn(v.y);
    __nv_bfloat16 h2 = __float2bfloat16_rn(v.z);
    __nv_bfloat16 h3 = __float2bfloat16_rn(v.w);
    __nv_bfloat16 l0 = __float2bfloat16_rn(v.x - __bfloat162float(h0));
    __nv_bfloat16 l1 = __float2bfloat16_rn(v.y - __bfloat162float(h1));
    __nv_bfloat16 l2 = __float2bfloat16_rn(v.z - __bfloat162float(h2));
    __nv_bfloat16 l3 = __float2bfloat16_rn(v.w - __bfloat162float(h3));
    ((__nv_bfloat162*)hi)[i*2]     = __nv_bfloat162(h0, h1);
    ((__nv_bfloat162*)hi)[i*2 + 1] = __nv_bfloat162(h2, h3);
    ((__nv_bfloat162*)lo)[i*2]     = __nv_bfloat162(l0, l1);
    ((__nv_bfloat162*)lo)[i*2 + 1] = __nv_bfloat162(l2, l3);
}

// ===========================================================================
// mma.sync bf16 GEMM: C[M,N] = A @ B^T, (hi,lo) 3-term accumulation.
// CTA 128x128, BK=32, 256 threads (8 warps, 2x4), warp tile 64x32.
// SMEM rows padded to 40 bf16 (80B) for conflict-free ldmatrix.
// Double-buffered cp.async pipeline.
// ===========================================================================
#define MM_PAD 40
#define MM_TILE (128 * MM_PAD * 2)          // 10240 B per tile
#define MM_BUF  (4 * MM_TILE)               // 40960 B per buffer
#define MM_SMEM (2 * MM_BUF)                // 81920 B

__global__ __launch_bounds__(256) void gemm_mma(
    const __nv_bfloat16* __restrict__ Ah, const __nv_bfloat16* __restrict__ Al,
    const __nv_bfloat16* __restrict__ Bh, const __nv_bfloat16* __restrict__ Bl,
    float* __restrict__ C, int M, int N, int K)
{
    extern __shared__ __align__(16) char smem[];
    const uint32_t sb = smem_to_u32(smem);
    const int tid = threadIdx.x;
    const int lane = tid & 31;
    const int wid = tid >> 5;
    const int warp_m = wid & 1;      // 0..1
    const int warp_n = wid >> 1;     // 0..3
    const int m0 = blockIdx.y * 128;
    const int n0 = blockIdx.x * 128;

    float acc[4][4][4];
#pragma unroll
    for (int i = 0; i < 4; i++)
#pragma unroll
        for (int j = 0; j < 4; j++)
#pragma unroll
            for (int k = 0; k < 4; k++) acc[i][j][k] = 0.f;

    // per-thread load coords: 512 uint4 per tile, 2 per thread
    const int r0 = tid >> 2, ch0 = (tid & 3);              // idx = tid
    const int r1 = (tid + 256) >> 2, ch1 = ((tid + 256) & 3);

    auto issue_loads = [&](int it) {
        const int kb = it * 32;
        const uint32_t b = sb + (it & 1) * MM_BUF;
        const uint32_t d0 = b + r0 * 80 + ch0 * 16;
        const uint32_t d1 = b + r1 * 80 + ch1 * 16;
        const size_t sa0 = (size_t)(m0 + r0) * K + kb + ch0 * 8;
        const size_t sa1 = (size_t)(m0 + r1) * K + kb + ch1 * 8;
        const size_t sb0 = (size_t)(n0 + r0) * K + kb + ch0 * 8;
        const size_t sb1 = (size_t)(n0 + r1) * K + kb + ch1 * 8;
        CP_ASYNC16(d0,                 Ah + sa0);
        CP_ASYNC16(d1,                 Ah + sa1);
        CP_ASYNC16(d0 + MM_TILE,       Al + sa0);
        CP_ASYNC16(d1 + MM_TILE,       Al + sa1);
        CP_ASYNC16(d0 + 2 * MM_TILE,   Bh + sb0);
        CP_ASYNC16(d1 + 2 * MM_TILE,   Bh + sb1);
        CP_ASYNC16(d0 + 3 * MM_TILE,   Bl + sb0);
        CP_ASYNC16(d1 + 3 * MM_TILE,   Bl + sb1);
        CP_COMMIT();
    };

    const int niter = K / 32;
    issue_loads(0);

    const int arow = warp_m * 64 + (lane & 15);
    const int acolh = (lane >> 4) * 8;                  // bf16 col within kstep
    const int brow = warp_n * 32 + (lane & 7);
    const int bcolh = ((lane >> 3) & 1) * 8;

    for (int it = 0; it < niter; it++) {
        if (it + 1 < niter) {
            issue_loads(it + 1);
            CP_WAIT(1);
        } else {
            CP_WAIT(0);
        }
        __syncthreads();

        const uint32_t b = sb + (it & 1) * MM_BUF;
#pragma unroll
        for (int ks = 0; ks < 32; ks += 16) {
            uint32_t ah[4][4], al[4][4], bh[4][2], bl[4][2];
#pragma unroll
            for (int mt = 0; mt < 4; mt++) {
                uint32_t addr = b + (arow + mt * 16) * 80 + (acolh + ks) * 2;
                ldmatrix_x4(ah[mt], addr);
                ldmatrix_x4(al[mt], addr + MM_TILE);
            }
#pragma unroll
            for (int nt = 0; nt < 4; nt++) {
                uint32_t addr = b + 2 * MM_TILE + (brow + nt * 8) * 80 + (bcolh + ks) * 2;
                ldmatrix_x2(bh[nt], addr);
                ldmatrix_x2(bl[nt], addr + MM_TILE);
            }
#pragma unroll
            for (int mt = 0; mt < 4; mt++)
#pragma unroll
                for (int nt = 0; nt < 4; nt++) {
                    mma_bf16(acc[mt][nt], ah[mt], bh[nt]);
                    mma_bf16(acc[mt][nt], ah[mt], bl[nt]);
                    mma_bf16(acc[mt][nt], al[mt], bh[nt]);
                }
        }
        __syncthreads();
    }

    // epilogue: direct float2 stores
    const int tr = lane >> 2, tc = (lane & 3) * 2;
#pragma unroll
    for (int mt = 0; mt < 4; mt++) {
#pragma unroll
        for (int nt = 0; nt < 4; nt++) {
            int row = m0 + warp_m * 64 + mt * 16 + tr;
            int col = n0 + warp_n * 32 + nt * 8 + tc;
            *(float2*)&C[(size_t)row * N + col] =
                make_float2(acc[mt][nt][0], acc[mt][nt][1]);
            *(float2*)&C[(size_t)(row + 8) * N + col] =
                make_float2(acc[mt][nt][2], acc[mt][nt][3]);
        }
    }
}

// ===========================================================================
// RoPE, half-split pairing, REVERSED rotation (verified correct)
// ===========================================================================
__global__ void rope_rev_kernel(float* __restrict__ qkv,
                                const int* __restrict__ start_pos)
{
    const int half = DD / 2;
    int idx = blockIdx.x * blockDim.x + threadIdx.x;
    int total = NTOK * HH * half;
    if (idx >= total) return;

    int i = idx % half;
    int h = (idx / half) % HH;
    int n = idx / (half * HH);
    int t = n % TT;

    double pos = (double)(*start_pos + t);
    double inv_freq = exp2(-(double)i * (13.287712379549449 / 64.0));
    double ang = pos * inv_freq;
    const double TWOPI = 6.283185307179586476925286766559;
    ang -= floor(ang / TWOPI) * TWOPI;
    float c, s;
    sincosf((float)ang, &c, &s);

    float* qrow = qkv + (size_t)n * C3 + h * DD;
    float* krow = qrow + CC;

    float q1 = qrow[i], q2 = qrow[i + half];
    qrow[i]        =  q1 * c + q2 * s;
    qrow[i + half] = -q1 * s + q2 * c;

    float k1 = krow[i], k2 = krow[i + half];
    krow[i]        =  k1 * c + k2 * s;
    krow[i + half] = -k1 * s + k2 * c;
}

// ===========================================================================
// Causal flash attention, fp32 (verified correct)
// ===========================================================================
#define AT_BM 64
#define AT_BN 32

__global__ __launch_bounds__(256) void attn_kernel(
    const float* __restrict__ qkv, float* __restrict__ out)
{
    __shared__ float Ks[AT_BN][DD];
    __shared__ float Vs[AT_BN][DD];

    const int q0 = ((int)gridDim.x - 1 - (int)blockIdx.x) * AT_BM;
    const int bh = blockIdx.y;
    const int b = bh / HH, h = bh % HH;
    const int tid = threadIdx.x;
    const int r = tid >> 2;
    const int lane4 = tid & 3;

    const float scale = 0.08838834764831845f;
    const int qrow = q0 + r;

    const float* qptr = qkv + ((size_t)(b * TT + qrow)) * C3 + h * DD;
    float qreg[32];
#pragma unroll
    for (int i = 0; i < 8; i++) {
        float4 v = *(const float4*)&qptr[4 * (lane4 + 4 * i)];
        qreg[4*i+0] = v.x * scale; qreg[4*i+1] = v.y * scale;
        qreg[4*i+2] = v.z * scale; qreg[4*i+3] = v.w * scale;
    }

    float o[32];
#pragma unroll
    for (int i = 0; i < 32; i++) o[i] = 0.f;
    float m = -1e30f, l = 0.f;

    const float* kbase = qkv + ((size_t)(b * TT)) * C3 + CC     + h * DD;
    const float* vbase = qkv + ((size_t)(b * TT)) * C3 + 2 * CC + h * DD;

    const int kv_end = q0 + AT_BM;
    for (int j0 = 0; j0 < kv_end; j0 += AT_BN) {
        __syncthreads();
#pragma unroll
        for (int it = 0; it < 4; it++) {
            int idx = tid + it * 256;
            int row = idx >> 5;
            int col = idx & 31;
            *(float4*)&Ks[row][col * 4] =
                *(const float4*)&kbase[(size_t)(j0 + row) * C3 + col * 4];
            *(float4*)&Vs[row][col * 4] =
                *(const float4*)&vbase[(size_t)(j0 + row) * C3 + col * 4];
        }
        __syncthreads();

        float s[AT_BN];
#pragma unroll
        for (int j = 0; j < AT_BN; j++) {
            float acc = 0.f;
#pragma unroll
            for (int i = 0; i < 8; i++) {
                const float4 kv4 = *(const float4*)&Ks[j][4 * (lane4 + 4 * i)];
                acc += qreg[4*i+0] * kv4.x + qreg[4*i+1] * kv4.y
                     + qreg[4*i+2] * kv4.z + qreg[4*i+3] * kv4.w;
            }
            acc += __shfl_xor_sync(0xffffffffu, acc, 1);
            acc += __shfl_xor_sync(0xffffffffu, acc, 2);
            s[j] = (j0 + j <= qrow) ? acc : -1e30f;
        }

        float tm = m;
#pragma unroll
        for (int j = 0; j < AT_BN; j++) tm = fmaxf(tm, s[j]);
        float corr = __expf(m - tm);
        m = tm;
        l *= corr;
#pragma unroll
        for (int i = 0; i < 32; i++) o[i] *= corr;
#pragma unroll
        for (int j = 0; j < AT_BN; j++) {
            float p = __expf(s[j] - m);
            l += p;
            s[j] = p;
        }
#pragma unroll
        for (int j = 0; j < AT_BN; j++) {
            float p = s[j];
#pragma unroll
            for (int i = 0; i < 8; i++) {
                const float4 v4 = *(const float4*)&Vs[j][4 * (lane4 + 4 * i)];
                o[4*i+0] += p * v4.x; o[4*i+1] += p * v4.y;
                o[4*i+2] += p * v4.z; o[4*i+3] += p * v4.w;
            }
        }
    }

    const float inv_l = 1.f / l;
    float* optr = out + ((size_t)(b * TT + qrow)) * CC + h * DD;
#pragma unroll
    for (int i = 0; i < 8; i++) {
        float4 v = make_float4(o[4*i] * inv_l, o[4*i+1] * inv_l,
                               o[4*i+2] * inv_l, o[4*i+3] * inv_l);
        *(float4*)&optr[4 * (lane4 + 4 * i)] = v;
    }
}

// ===========================================================================
extern "C" void kernel_launch(void* const* d_in, const int* in_sizes, int n_in,
                              void* d_out, int out_size)
{
    const float* x = nullptr;
    const float* Wqkv = nullptr;
    const float* Wproj = nullptr;
    const int* start_pos = nullptr;
    for (int i = 0; i < n_in; i++) {
        long long sz = in_sizes[i];
        if (sz == (long long)NTOK * CC)      x = (const float*)d_in[i];
        else if (sz == (long long)C3 * CC)   Wqkv = (const float*)d_in[i];
        else if (sz == (long long)CC * CC)   Wproj = (const float*)d_in[i];
        else if (sz == 1)                    start_pos = (const int*)d_in[i];
    }
    if (n_in != 4 || !x || !Wqkv || !Wproj || !start_pos ||
        out_size != NTOK * CC)
        return;

    float* out = (float*)d_out;

    void* p;
    cudaGetSymbolAddress(&p, g_qkv);  float* qkv  = (float*)p;
    cudaGetSymbolAddress(&p, g_attn); float* attn = (float*)p;
    cudaGetSymbolAddress(&p, g_xh);   __nv_bfloat16* xh  = (__nv_bfloat16*)p;
    cudaGetSymbolAddress(&p, g_xl);   __nv_bfloat16* xl  = (__nv_bfloat16*)p;
    cudaGetSymbolAddress(&p, g_wqh);  __nv_bfloat16* wqh = (__nv_bfloat16*)p;
    cudaGetSymbolAddress(&p, g_wql);  __nv_bfloat16* wql = (__nv_bfloat16*)p;
    cudaGetSymbolAddress(&p, g_wph);  __nv_bfloat16* wph = (__nv_bfloat16*)p;
    cudaGetSymbolAddress(&p, g_wpl);  __nv_bfloat16* wpl = (__nv_bfloat16*)p;
    cudaGetSymbolAddress(&p, g_ah);   __nv_bfloat16* ah  = (__nv_bfloat16*)p;
    cudaGetSymbolAddress(&p, g_al);   __nv_bfloat16* al  = (__nv_bfloat16*)p;

    cudaFuncSetAttribute(gemm_mma, cudaFuncAttributeMaxDynamicSharedMemorySize, MM_SMEM);

    // 0) split inputs to bf16 hi/lo
    {
        int n4;
        n4 = NTOK * CC / 4; split_bf16<<<(n4 + 255)/256, 256>>>(x,     xh,  xl,  n4);
        n4 = C3 * CC / 4;   split_bf16<<<(n4 + 255)/256, 256>>>(Wqkv,  wqh, wql, n4);
        n4 = CC * CC / 4;   split_bf16<<<(n4 + 255)/256, 256>>>(Wproj, wph, wpl, n4);
    }

    // 1) qkv = x @ Wqkv^T  (tensor cores, bf16x3)
    gemm_mma<<<dim3(C3 / 128, NTOK / 128), 256, MM_SMEM>>>(
        xh, xl, wqh, wql, qkv, NTOK, C3, CC);

    // 2) RoPE (reversed rotation — verified)
    {
        int total = NTOK * HH * (DD / 2);
        rope_rev_kernel<<<(total + 255) / 256, 256>>>(qkv, start_pos);
    }

    // 3) causal flash attention
    attn_kernel<<<dim3(TT / AT_BM, BB * HH), 256>>>(qkv, attn);

    // 4) out = attn @ Wproj^T  (tensor cores, bf16x3)
    {
        int n4 = NTOK * CC / 4;
        split_bf16<<<(n4 + 255)/256, 256>>>(attn, ah, al, n4);
    }
    gemm_mma<<<dim3(CC / 128, NTOK / 128), 256, MM_SMEM>>>(
        ah, al, wph, wpl, out, NTOK, CC, CC);
}

// round 16
// speedup vs baseline: 3.1876x; 2.1483x over previous
#include <cuda_runtime.h>
#include <cuda_bf16.h>
#include <math.h>
#include <stdint.h>

// Problem constants
#define BB 2
#define TT 2048
#define CC 2048
#define HH 16
#define DD 128
#define NTOK (BB*TT)      // 4096
#define C3 (3*CC)         // 6144

// fp32 scratch
__device__ float g_qkv[(size_t)NTOK * C3];
__device__ float g_attn[(size_t)NTOK * CC];
// bf16 hi/lo scratch
__device__ __nv_bfloat16 g_xh[(size_t)NTOK * CC],  g_xl[(size_t)NTOK * CC];
__device__ __nv_bfloat16 g_wqh[(size_t)C3 * CC],   g_wql[(size_t)C3 * CC];
__device__ __nv_bfloat16 g_wph[(size_t)CC * CC],   g_wpl[(size_t)CC * CC];
__device__ __nv_bfloat16 g_ah[(size_t)NTOK * CC],  g_al[(size_t)NTOK * CC];

// ===========================================================================
// helpers
// ===========================================================================
__device__ __forceinline__ uint32_t smem_to_u32(const void* p) {
    uint32_t a;
    asm("{ .reg .u64 t; cvta.to.shared.u64 t, %1; cvt.u32.u64 %0, t; }"
        : "=r"(a) : "l"(p));
    return a;
}
__device__ __forceinline__ void ldmatrix_x4(uint32_t* r, uint32_t addr) {
    asm volatile("ldmatrix.sync.aligned.m8n8.x4.shared.b16 {%0,%1,%2,%3}, [%4];"
                 : "=r"(r[0]), "=r"(r[1]), "=r"(r[2]), "=r"(r[3]) : "r"(addr));
}
__device__ __forceinline__ void ldmatrix_x4t(uint32_t* r, uint32_t addr) {
    asm volatile("ldmatrix.sync.aligned.m8n8.x4.trans.shared.b16 {%0,%1,%2,%3}, [%4];"
                 : "=r"(r[0]), "=r"(r[1]), "=r"(r[2]), "=r"(r[3]) : "r"(addr));
}
__device__ __forceinline__ void ldmatrix_x2(uint32_t* r, uint32_t addr) {
    asm volatile("ldmatrix.sync.aligned.m8n8.x2.shared.b16 {%0,%1}, [%2];"
                 : "=r"(r[0]), "=r"(r[1]) : "r"(addr));
}
__device__ __forceinline__ void mma_bf16(float* c, const uint32_t* a, const uint32_t* b) {
    asm volatile(
        "mma.sync.aligned.m16n8k16.row.col.f32.bf16.bf16.f32 "
        "{%0,%1,%2,%3}, {%4,%5,%6,%7}, {%8,%9}, {%0,%1,%2,%3};"
        : "+f"(c[0]), "+f"(c[1]), "+f"(c[2]), "+f"(c[3])
        : "r"(a[0]), "r"(a[1]), "r"(a[2]), "r"(a[3]), "r"(b[0]), "r"(b[1]));
}
__device__ __forceinline__ uint32_t pack_bf16(float a, float b) {
    __nv_bfloat162 t(__float2bfloat16_rn(a), __float2bfloat16_rn(b));
    return *(uint32_t*)&t;
}
#define CP_ASYNC16(dst_u32, src) \
    asm volatile("cp.async.cg.shared.global [%0], [%1], 16;" \
                 :: "r"(dst_u32), "l"(src) : "memory")
#define CP_COMMIT() asm volatile("cp.async.commit_group;" ::: "memory")
#define CP_WAIT(n)  asm volatile("cp.async.wait_group %0;" :: "n"(n) : "memory")

// ===========================================================================
// fp32 -> bf16 hi/lo split
// ===========================================================================
__global__ __launch_bounds__(256) void split_bf16(
    const float* __restrict__ in, __nv_bfloat16* __restrict__ hi,
    __nv_bfloat16* __restrict__ lo, int n4)
{
    int i = blockIdx.x * blockDim.x + threadIdx.x;
    if (i >= n4) return;
    float4 v = ((const float4*)in)[i];
    __nv_bfloat16 h0 = __float2bfloat16_rn(v.x);
    __nv_bfloat16 h1 = __float2bfloat16_rn(v.y);
    __nv_bfloat16 h2 = __float2bfloat16_rn(v.z);
    __nv_bfloat16 h3 = __float2bfloat16_rn(v.w);
    __nv_bfloat16 l0 = __float2bfloat16_rn(v.x - __bfloat162float(h0));
    __nv_bfloat16 l1 = __float2bfloat16_rn(v.y - __bfloat162float(h1));
    __nv_bfloat16 l2 = __float2bfloat16_rn(v.z - __bfloat162float(h2));
    __nv_bfloat16 l3 = __float2bfloat16_rn(v.w - __bfloat162float(h3));
    ((__nv_bfloat162*)hi)[i*2]     = __nv_bfloat162(h0, h1);
    ((__nv_bfloat162*)hi)[i*2 + 1] = __nv_bfloat162(h2, h3);
    ((__nv_bfloat162*)lo)[i*2]     = __nv_bfloat162(l0, l1);
    ((__nv_bfloat162*)lo)[i*2 + 1] = __nv_bfloat162(l2, l3);
}

// ===========================================================================
// mma.sync bf16 GEMM (hi/lo 3-term), CTA 128x128, BK=32, 256 thr, 8 warps.
// __launch_bounds__(256,2): cap regs at 128 so 2 CTAs co-reside per SM.
// ===========================================================================
#define MM_PAD 40
#define MM_TILE (128 * MM_PAD * 2)
#define MM_BUF  (4 * MM_TILE)
#define MM_SMEM (2 * MM_BUF)

__global__ __launch_bounds__(256, 2) void gemm_mma(
    const __nv_bfloat16* __restrict__ Ah, const __nv_bfloat16* __restrict__ Al,
    const __nv_bfloat16* __restrict__ Bh, const __nv_bfloat16* __restrict__ Bl,
    float* __restrict__ C, int M, int N, int K)
{
    extern __shared__ __align__(16) char smem[];
    const uint32_t sb = smem_to_u32(smem);
    const int tid = threadIdx.x;
    const int lane = tid & 31;
    const int wid = tid >> 5;
    const int warp_m = wid & 1;
    const int warp_n = wid >> 1;
    const int m0 = blockIdx.y * 128;
    const int n0 = blockIdx.x * 128;

    float acc[4][4][4];
#pragma unroll
    for (int i = 0; i < 4; i++)
#pragma unroll
        for (int j = 0; j < 4; j++)
#pragma unroll
            for (int k = 0; k < 4; k++) acc[i][j][k] = 0.f;

    const int r0 = tid >> 2, ch0 = (tid & 3);
    const int r1 = (tid + 256) >> 2, ch1 = ((tid + 256) & 3);

    auto issue_loads = [&](int it) {
        const int kb = it * 32;
        const uint32_t b = sb + (it & 1) * MM_BUF;
        const uint32_t d0 = b + r0 * 80 + ch0 * 16;
        const uint32_t d1 = b + r1 * 80 + ch1 * 16;
        const size_t sa0 = (size_t)(m0 + r0) * K + kb + ch0 * 8;
        const size_t sa1 = (size_t)(m0 + r1) * K + kb + ch1 * 8;
        const size_t sb0 = (size_t)(n0 + r0) * K + kb + ch0 * 8;
        const size_t sb1 = (size_t)(n0 + r1) * K + kb + ch1 * 8;
        CP_ASYNC16(d0,                 Ah + sa0);
        CP_ASYNC16(d1,                 Ah + sa1);
        CP_ASYNC16(d0 + MM_TILE,       Al + sa0);
        CP_ASYNC16(d1 + MM_TILE,       Al + sa1);
        CP_ASYNC16(d0 + 2 * MM_TILE,   Bh + sb0);
        CP_ASYNC16(d1 + 2 * MM_TILE,   Bh + sb1);
        CP_ASYNC16(d0 + 3 * MM_TILE,   Bl + sb0);
        CP_ASYNC16(d1 + 3 * MM_TILE,   Bl + sb1);
        CP_COMMIT();
    };

    const int niter = K / 32;
    issue_loads(0);

    const int arow = warp_m * 64 + (lane & 15);
    const int acolh = (lane >> 4) * 8;
    const int brow = warp_n * 32 + (lane & 7);
    const int bcolh = ((lane >> 3) & 1) * 8;

    for (int it = 0; it < niter; it++) {
        if (it + 1 < niter) {
            issue_loads(it + 1);
            CP_WAIT(1);
        } else {
            CP_WAIT(0);
        }
        __syncthreads();

        const uint32_t b = sb + (it & 1) * MM_BUF;
#pragma unroll
        for (int ks = 0; ks < 32; ks += 16) {
            uint32_t ah[4][4], al[4][4], bh[4][2], bl[4][2];
#pragma unroll
            for (int mt = 0; mt < 4; mt++) {
                uint32_t addr = b + (arow + mt * 16) * 80 + (acolh + ks) * 2;
                ldmatrix_x4(ah[mt], addr);
                ldmatrix_x4(al[mt], addr + MM_TILE);
            }
#pragma unroll
            for (int nt = 0; nt < 4; nt++) {
                uint32_t addr = b + 2 * MM_TILE + (brow + nt * 8) * 80 + (bcolh + ks) * 2;
                ldmatrix_x2(bh[nt], addr);
                ldmatrix_x2(bl[nt], addr + MM_TILE);
            }
#pragma unroll
            for (int mt = 0; mt < 4; mt++)
#pragma unroll
                for (int nt = 0; nt < 4; nt++) {
                    mma_bf16(acc[mt][nt], ah[mt], bh[nt]);
                    mma_bf16(acc[mt][nt], ah[mt], bl[nt]);
                    mma_bf16(acc[mt][nt], al[mt], bh[nt]);
                }
        }
        __syncthreads();
    }

    const int tr = lane >> 2, tc = (lane & 3) * 2;
#pragma unroll
    for (int mt = 0; mt < 4; mt++) {
#pragma unroll
        for (int nt = 0; nt < 4; nt++) {
            int row = m0 + warp_m * 64 + mt * 16 + tr;
            int col = n0 + warp_n * 32 + nt * 8 + tc;
            *(float2*)&C[(size_t)row * N + col] =
                make_float2(acc[mt][nt][0], acc[mt][nt][1]);
            *(float2*)&C[(size_t)(row + 8) * N + col] =
                make_float2(acc[mt][nt][2], acc[mt][nt][3]);
        }
    }
}

// ===========================================================================
// RoPE, half-split pairing, REVERSED rotation (verified correct)
// ===========================================================================
__global__ void rope_rev_kernel(float* __restrict__ qkv,
                                const int* __restrict__ start_pos)
{
    const int half = DD / 2;
    int idx = blockIdx.x * blockDim.x + threadIdx.x;
    int total = NTOK * HH * half;
    if (idx >= total) return;

    int i = idx % half;
    int h = (idx / half) % HH;
    int n = idx / (half * HH);
    int t = n % TT;

    double pos = (double)(*start_pos + t);
    double inv_freq = exp2(-(double)i * (13.287712379549449 / 64.0));
    double ang = pos * inv_freq;
    const double TWOPI = 6.283185307179586476925286766559;
    ang -= floor(ang / TWOPI) * TWOPI;
    float c, s;
    sincosf((float)ang, &c, &s);

    float* qrow = qkv + (size_t)n * C3 + h * DD;
    float* krow = qrow + CC;

    float q1 = qrow[i], q2 = qrow[i + half];
    qrow[i]        =  q1 * c + q2 * s;
    qrow[i + half] = -q1 * s + q2 * c;

    float k1 = krow[i], k2 = krow[i + half];
    krow[i]        =  k1 * c + k2 * s;
    krow[i + half] = -k1 * s + k2 * c;
}

// ===========================================================================
// Tensor-core causal flash attention (hi/lo bf16, 3-term QK and PV).
// Block: 128 thr (4 warps). Q tile 64 rows (16/warp), KV tiles 64.
// SMEM: Qh,Ql,Kh,Kl,Vh,Vl, each 64 x 136 bf16 (272B padded rows).
// ===========================================================================
#define FA_PD 136
#define FA_TILE (64 * FA_PD * 2)     // 17408 B
#define FA_SMEM (6 * FA_TILE)        // 104448 B

__device__ __forceinline__ void split_store8(char* ph, float4 v) {
    __nv_bfloat16 h0 = __float2bfloat16_rn(v.x), h1 = __float2bfloat16_rn(v.y);
    __nv_bfloat16 h2 = __float2bfloat16_rn(v.z), h3 = __float2bfloat16_rn(v.w);
    __nv_bfloat16 l0 = __float2bfloat16_rn(v.x - __bfloat162float(h0));
    __nv_bfloat16 l1 = __float2bfloat16_rn(v.y - __bfloat162float(h1));
    __nv_bfloat16 l2 = __float2bfloat16_rn(v.z - __bfloat162float(h2));
    __nv_bfloat16 l3 = __float2bfloat16_rn(v.w - __bfloat162float(h3));
    ((__nv_bfloat162*)ph)[0] = __nv_bfloat162(h0, h1);
    ((__nv_bfloat162*)ph)[1] = __nv_bfloat162(h2, h3);
    ((__nv_bfloat162*)(ph + FA_TILE))[0] = __nv_bfloat162(l0, l1);
    ((__nv_bfloat162*)(ph + FA_TILE))[1] = __nv_bfloat162(l2, l3);
}

__global__ __launch_bounds__(128) void attn_tc(
    const float* __restrict__ qkv, float* __restrict__ out)
{
    extern __shared__ __align__(16) char smem[];
    const uint32_t sb = smem_to_u32(smem);
    const uint32_t sQh = sb;
    const uint32_t sKh = sb + 2 * FA_TILE;
    const uint32_t sVh = sb + 4 * FA_TILE;

    const int tid = threadIdx.x, lane = tid & 31, w = tid >> 5;
    const int q0 = ((int)gridDim.x - 1 - (int)blockIdx.x) * 64;
    const int bh = blockIdx.y;
    const int b = bh >> 4, h = bh & 15;

    const float scale = 0.08838834764831845f;
    const float* Qg = qkv + (size_t)(b * TT + q0) * C3 + h * DD;
    const float* Kg = qkv + (size_t)(b * TT) * C3 + CC + h * DD;
    const float* Vg = qkv + (size_t)(b * TT) * C3 + 2 * CC + h * DD;

    // Q tile: scale folded, split to hi/lo
#pragma unroll
    for (int i = 0; i < 16; i++) {
        int idx = tid + i * 128;
        int row = idx >> 5, c4 = (idx & 31) << 2;
        float4 v = *(const float4*)&Qg[(size_t)row * C3 + c4];
        v.x *= scale; v.y *= scale; v.z *= scale; v.w *= scale;
        split_store8(smem + 0 * FA_TILE + row * 272 + c4 * 2, v);
    }

    float o[16][4];
#pragma unroll
    for (int i = 0; i < 16; i++)
#pragma unroll
        for (int j = 0; j < 4; j++) o[i][j] = 0.f;
    float m0 = -1e30f, m1 = -1e30f, l0 = 0.f, l1 = 0.f;

    // ldmatrix address components (constant per thread)
    const uint32_t qa = sQh + (w * 16 + (lane & 15)) * 272 + (lane >> 4) * 16;
    const int krow_off = (lane & 7) + 8 * (lane >> 4);
    const int kcol_off = 8 * ((lane >> 3) & 1);
    const int vrow_off = (lane & 7) + 8 * ((lane >> 3) & 1);
    const int vcol_off = 8 * (lane >> 4);

    const int kv_end = q0 + 64;
    for (int j0 = 0; j0 < kv_end; j0 += 64) {
        __syncthreads();
#pragma unroll
        for (int i = 0; i < 16; i++) {
            int idx = tid + i * 128;
            int row = idx >> 5, c4 = (idx & 31) << 2;
            float4 kv4 = *(const float4*)&Kg[(size_t)(j0 + row) * C3 + c4];
            split_store8(smem + 2 * FA_TILE + row * 272 + c4 * 2, kv4);
            float4 vv4 = *(const float4*)&Vg[(size_t)(j0 + row) * C3 + c4];
            split_store8(smem + 4 * FA_TILE + row * 272 + c4 * 2, vv4);
        }
        __syncthreads();

        // ---- S = Qs @ K^T (3-term) ----
        float s[8][4];
#pragma unroll
        for (int nt = 0; nt < 8; nt++)
#pragma unroll
            for (int j = 0; j < 4; j++) s[nt][j] = 0.f;

#pragma unroll
        for (int ks = 0; ks < 8; ks++) {
            uint32_t aqh[4], aql[4];
            uint32_t qaddr = qa + ks * 32;
            ldmatrix_x4(aqh, qaddr);
            ldmatrix_x4(aql, qaddr + FA_TILE);
#pragma unroll
            for (int nt2 = 0; nt2 < 4; nt2++) {
                uint32_t bkh[4], bkl[4];
                uint32_t kaddr = sKh + (nt2 * 16 + krow_off) * 272 + (ks * 16 + kcol_off) * 2;
                ldmatrix_x4(bkh, kaddr);
                ldmatrix_x4(bkl, kaddr + FA_TILE);
                mma_bf16(s[2*nt2],   aqh, &bkh[0]);
                mma_bf16(s[2*nt2],   aqh, &bkl[0]);
                mma_bf16(s[2*nt2],   aql, &bkh[0]);
                mma_bf16(s[2*nt2+1], aqh, &bkh[2]);
                mma_bf16(s[2*nt2+1], aqh, &bkl[2]);
                mma_bf16(s[2*nt2+1], aql, &bkh[2]);
            }
        }

        // causal mask (diagonal tile only)
        if (j0 == q0) {
            int rl0 = w * 16 + (lane >> 2);
            int cb = (lane & 3) * 2;
#pragma unroll
            for (int nt = 0; nt < 8; nt++) {
                int cg = nt * 8 + cb;
                if (cg     > rl0)     s[nt][0] = -1e30f;
                if (cg + 1 > rl0)     s[nt][1] = -1e30f;
                if (cg     > rl0 + 8) s[nt][2] = -1e30f;
                if (cg + 1 > rl0 + 8) s[nt][3] = -1e30f;
            }
        }

        // ---- online softmax ----
        float mx0 = m0, mx1 = m1;
#pragma unroll
        for (int nt = 0; nt < 8; nt++) {
            mx0 = fmaxf(mx0, fmaxf(s[nt][0], s[nt][1]));
            mx1 = fmaxf(mx1, fmaxf(s[nt][2], s[nt][3]));
        }
        mx0 = fmaxf(mx0, __shfl_xor_sync(0xffffffffu, mx0, 1));
        mx0 = fmaxf(mx0, __shfl_xor_sync(0xffffffffu, mx0, 2));
        mx1 = fmaxf(mx1, __shfl_xor_sync(0xffffffffu, mx1, 1));
        mx1 = fmaxf(mx1, __shfl_xor_sync(0xffffffffu, mx1, 2));

        float c0 = __expf(m0 - mx0), c1 = __expf(m1 - mx1);
        m0 = mx0; m1 = mx1;
        l0 *= c0; l1 *= c1;
#pragma unroll
        for (int dnt = 0; dnt < 16; dnt++) {
            o[dnt][0] *= c0; o[dnt][1] *= c0;
            o[dnt][2] *= c1; o[dnt][3] *= c1;
        }

        // p = exp(s - m), packed as A-frags (hi/lo)
        uint32_t pAh[4][4], pAl[4][4];
        float rs0 = 0.f, rs1 = 0.f;
#pragma unroll
        for (int nt = 0; nt < 8; nt++) {
            float p0 = __expf(s[nt][0] - m0);
            float p1 = __expf(s[nt][1] - m0);
            float p2 = __expf(s[nt][2] - m1);
            float p3 = __expf(s[nt][3] - m1);
            rs0 += p0 + p1;
            rs1 += p2 + p3;
            __nv_bfloat16 h0 = __float2bfloat16_rn(p0), h1 = __float2bfloat16_rn(p1);
            __nv_bfloat16 h2 = __float2bfloat16_rn(p2), h3 = __float2bfloat16_rn(p3);
            int kk = nt >> 1, hf = (nt & 1) * 2;
            {
                __nv_bfloat162 t01(h0, h1), t23(h2, h3);
                pAh[kk][hf + 0] = *(uint32_t*)&t01;
                pAh[kk][hf + 1] = *(uint32_t*)&t23;
            }
            pAl[kk][hf + 0] = pack_bf16(p0 - __bfloat162float(h0),
                                        p1 - __bfloat162float(h1));
            pAl[kk][hf + 1] = pack_bf16(p2 - __bfloat162float(h2),
                                        p3 - __bfloat162float(h3));
        }
        l0 += rs0; l1 += rs1;

        // ---- O += P @ V (3-term) ----
#pragma unroll
        for (int kk = 0; kk < 4; kk++) {
#pragma unroll
            for (int dt2 = 0; dt2 < 8; dt2++) {
                uint32_t vh4[4], vl4[4];
                uint32_t vaddr = sVh + (kk * 16 + vrow_off) * 272 + (dt2 * 16 + vcol_off) * 2;
                ldmatrix_x4t(vh4, vaddr);
                ldmatrix_x4t(vl4, vaddr + FA_TILE);
                mma_bf16(o[2*dt2],   pAh[kk], &vh4[0]);
                mma_bf16(o[2*dt2],   pAh[kk], &vl4[0]);
                mma_bf16(o[2*dt2],   pAl[kk], &vh4[0]);
                mma_bf16(o[2*dt2+1], pAh[kk], &vh4[2]);
                mma_bf16(o[2*dt2+1], pAh[kk], &vl4[2]);
                mma_bf16(o[2*dt2+1], pAl[kk], &vh4[2]);
            }
        }
    }

    // finalize
    l0 += __shfl_xor_sync(0xffffffffu, l0, 1);
    l0 += __shfl_xor_sync(0xffffffffu, l0, 2);
    l1 += __shfl_xor_sync(0xffffffffu, l1, 1);
    l1 += __shfl_xor_sync(0xffffffffu, l1, 2);
    const float inv0 = 1.f / l0, inv1 = 1.f / l1;

    const int row0 = q0 + w * 16 + (lane >> 2);
    const int c2 = (lane & 3) * 2;
    float* op0 = out + (size_t)(b * TT + row0) * CC + h * DD;
    float* op1 = op0 + 8 * CC;
#pragma unroll
    for (int dnt = 0; dnt < 16; dnt++) {
        int d = dnt * 8 + c2;
        *(float2*)&op0[d] = make_float2(o[dnt][0] * inv0, o[dnt][1] * inv0);
        *(float2*)&op1[d] = make_float2(o[dnt][2] * inv1, o[dnt][3] * inv1);
    }
}

// ===========================================================================
extern "C" void kernel_launch(void* const* d_in, const int* in_sizes, int n_in,
                              void* d_out, int out_size)
{
    const float* x = nullptr;
    const float* Wqkv = nullptr;
    const float* Wproj = nullptr;
    const int* start_pos = nullptr;
    for (int i = 0; i < n_in; i++) {
        long long sz = in_sizes[i];
        if (sz == (long long)NTOK * CC)      x = (const float*)d_in[i];
        else if (sz == (long long)C3 * CC)   Wqkv = (const float*)d_in[i];
        else if (sz == (long long)CC * CC)   Wproj = (const float*)d_in[i];
        else if (sz == 1)                    start_pos = (const int*)d_in[i];
    }
    if (n_in != 4 || !x || !Wqkv || !Wproj || !start_pos ||
        out_size != NTOK * CC)
        return;

    float* out = (float*)d_out;

    void* p;
    cudaGetSymbolAddress(&p, g_qkv);  float* qkv  = (float*)p;
    cudaGetSymbolAddress(&p, g_attn); float* attn = (float*)p;
    cudaGetSymbolAddress(&p, g_xh);   __nv_bfloat16* xh  = (__nv_bfloat16*)p;
    cudaGetSymbolAddress(&p, g_xl);   __nv_bfloat16* xl  = (__nv_bfloat16*)p;
    cudaGetSymbolAddress(&p, g_wqh);  __nv_bfloat16* wqh = (__nv_bfloat16*)p;
    cudaGetSymbolAddress(&p, g_wql);  __nv_bfloat16* wql = (__nv_bfloat16*)p;
    cudaGetSymbolAddress(&p, g_wph);  __nv_bfloat16* wph = (__nv_bfloat16*)p;
    cudaGetSymbolAddress(&p, g_wpl);  __nv_bfloat16* wpl = (__nv_bfloat16*)p;
    cudaGetSymbolAddress(&p, g_ah);   __nv_bfloat16* ah  = (__nv_bfloat16*)p;
    cudaGetSymbolAddress(&p, g_al);   __nv_bfloat16* al  = (__nv_bfloat16*)p;

    cudaFuncSetAttribute(gemm_mma, cudaFuncAttributeMaxDynamicSharedMemorySize, MM_SMEM);
    cudaFuncSetAttribute(attn_tc,  cudaFuncAttributeMaxDynamicSharedMemorySize, FA_SMEM);

    // 0) split inputs to bf16 hi/lo
    {
        int n4;
        n4 = NTOK * CC / 4; split_bf16<<<(n4 + 255)/256, 256>>>(x,     xh,  xl,  n4);
        n4 = C3 * CC / 4;   split_bf16<<<(n4 + 255)/256, 256>>>(Wqkv,  wqh, wql, n4);
        n4 = CC * CC / 4;   split_bf16<<<(n4 + 255)/256, 256>>>(Wproj, wph, wpl, n4);
    }

    // 1) qkv = x @ Wqkv^T  (tensor cores)
    gemm_mma<<<dim3(C3 / 128, NTOK / 128), 256, MM_SMEM>>>(
        xh, xl, wqh, wql, qkv, NTOK, C3, CC);

    // 2) RoPE (reversed rotation — verified)
    {
        int total = NTOK * HH * (DD / 2);
        rope_rev_kernel<<<(total + 255) / 256, 256>>>(qkv, start_pos);
    }

    // 3) causal flash attention (tensor cores)
    attn_tc<<<dim3(TT / 64, BB * HH), 128, FA_SMEM>>>(qkv, attn);

    // 4) out = attn @ Wproj^T  (tensor cores)
    {
        int n4 = NTOK * CC / 4;
        split_bf16<<<(n4 + 255)/256, 256>>>(attn, ah, al, n4);
    }
    gemm_mma<<<dim3(CC / 128, NTOK / 128), 256, MM_SMEM>>>(
        ah, al, wph, wpl, out, NTOK, CC, CC);
}